// round 1
// baseline (speedup 1.0000x reference)
#include <cuda_runtime.h>
#include <cstdint>

// VectorQuantize: B x D rows, K x D codebook, D=64, K=512.
// out[0 : B*D)       = z_q_x     = fl(z + fl(q - z))   (replicates jax straight-through arithmetic)
// out[B*D : 2*B*D)   = z_q_x_grd = q                    (exact codebook row)
//
// Distance replicates reference rounding order:
//   m    = z . c                (fp32 accumulate, pairwise f32x2 then horizontal)
//   t    = fl(z_sq - 2*m)       (2*m exact)
//   dist = fl(t + c_sq)
// argmin with strict '<' scanning k ascending -> first index wins ties (jnp.argmin).

#define VQ_K   512
#define VQ_D   64
#define VQ_TPB 256

typedef unsigned long long ull;

__device__ __forceinline__ ull vq_fma2(ull a, ull b, ull c) {
    ull d;
    asm("fma.rn.f32x2 %0, %1, %2, %3;" : "=l"(d) : "l"(a), "l"(b), "l"(c));
    return d;
}
__device__ __forceinline__ ull vq_add2(ull a, ull b) {
    ull d;
    asm("add.rn.f32x2 %0, %1, %2;" : "=l"(d) : "l"(a), "l"(b));
    return d;
}
__device__ __forceinline__ float2 vq_unpack(ull a) {
    float2 f;
    asm("mov.b64 {%0, %1}, %2;" : "=f"(f.x), "=f"(f.y) : "l"(a));
    return f;
}

// dynamic smem: K*D codebook floats + K c_sq floats
#define VQ_SMEM_BYTES ((VQ_K * VQ_D + VQ_K) * 4)

__global__ void __launch_bounds__(VQ_TPB, 1)
vq_kernel(const float* __restrict__ z, const float* __restrict__ cb,
          float* __restrict__ out, int B) {
    extern __shared__ float smem[];
    float* s_cb  = smem;              // [K*D]
    float* s_csq = smem + VQ_K * VQ_D; // [K]

    const int tid = threadIdx.x;

    // ---- stage codebook into smem (coalesced float4) ----
    {
        const float4* g4 = reinterpret_cast<const float4*>(cb);
        float4* s4 = reinterpret_cast<float4*>(s_cb);
        #pragma unroll 4
        for (int i = tid; i < (VQ_K * VQ_D) / 4; i += VQ_TPB) s4[i] = g4[i];
    }
    __syncthreads();

    // ---- c_sq per code ----
    for (int k = tid; k < VQ_K; k += VQ_TPB) {
        const float* c = s_cb + k * VQ_D;
        float s = 0.0f;
        #pragma unroll
        for (int d = 0; d < VQ_D; ++d) s = __fmaf_rn(c[d], c[d], s);
        s_csq[k] = s;
    }
    __syncthreads();

    const long long row = (long long)blockIdx.x * VQ_TPB + tid;
    if (row >= B) return;

    // ---- load z row into registers as 32 packed f32 pairs ----
    ull zr[32];
    {
        const ulonglong2* zp =
            reinterpret_cast<const ulonglong2*>(z + row * (long long)VQ_D);
        #pragma unroll
        for (int i = 0; i < 16; ++i) {
            ulonglong2 v = zp[i];
            zr[2 * i]     = v.x;
            zr[2 * i + 1] = v.y;
        }
    }

    // ---- z_sq ----
    float zsq;
    {
        ull a0 = 0, a1 = 0, a2 = 0, a3 = 0;
        #pragma unroll
        for (int i = 0; i < 32; i += 4) {
            a0 = vq_fma2(zr[i + 0], zr[i + 0], a0);
            a1 = vq_fma2(zr[i + 1], zr[i + 1], a1);
            a2 = vq_fma2(zr[i + 2], zr[i + 2], a2);
            a3 = vq_fma2(zr[i + 3], zr[i + 3], a3);
        }
        float2 s = vq_unpack(vq_add2(vq_add2(a0, a1), vq_add2(a2, a3)));
        zsq = __fadd_rn(s.x, s.y);
    }

    // ---- argmin over codes ----
    float best = __int_as_float(0x7f800000);  // +inf
    int bk = 0;
    #pragma unroll 1
    for (int k = 0; k < VQ_K; ++k) {
        const ulonglong2* c2 =
            reinterpret_cast<const ulonglong2*>(s_cb + (k << 6));
        ull acc0 = 0, acc1 = 0, acc2 = 0, acc3 = 0;
        #pragma unroll
        for (int i = 0; i < 16; i += 2) {
            ulonglong2 ca = c2[i];
            ulonglong2 cbv = c2[i + 1];
            acc0 = vq_fma2(zr[2 * i + 0], ca.x,  acc0);
            acc1 = vq_fma2(zr[2 * i + 1], ca.y,  acc1);
            acc2 = vq_fma2(zr[2 * i + 2], cbv.x, acc2);
            acc3 = vq_fma2(zr[2 * i + 3], cbv.y, acc3);
        }
        float2 sf = vq_unpack(vq_add2(vq_add2(acc0, acc1), vq_add2(acc2, acc3)));
        float dot  = __fadd_rn(sf.x, sf.y);
        float t    = __fsub_rn(zsq, __fmul_rn(2.0f, dot));
        float dist = __fadd_rn(t, s_csq[k]);
        bool p = dist < best;        // strict: first index wins ties
        best = p ? dist : best;
        bk   = p ? k : bk;
    }

    // ---- write outputs ----
    const float4* q4 = reinterpret_cast<const float4*>(s_cb + (bk << 6));
    float4* o1 = reinterpret_cast<float4*>(out + row * (long long)VQ_D);
    float4* o2 = reinterpret_cast<float4*>(out + (long long)B * VQ_D +
                                           row * (long long)VQ_D);
    #pragma unroll
    for (int i = 0; i < 16; ++i) {
        float4 qv = q4[i];
        float2 z0 = vq_unpack(zr[2 * i]);
        float2 z1 = vq_unpack(zr[2 * i + 1]);
        float4 w;
        w.x = __fadd_rn(z0.x, __fsub_rn(qv.x, z0.x));
        w.y = __fadd_rn(z0.y, __fsub_rn(qv.y, z0.y));
        w.z = __fadd_rn(z1.x, __fsub_rn(qv.z, z1.x));
        w.w = __fadd_rn(z1.y, __fsub_rn(qv.w, z1.y));
        o1[i] = w;
        o2[i] = qv;
    }
}

extern "C" void kernel_launch(void* const* d_in, const int* in_sizes, int n_in,
                              void* d_out, int out_size) {
    const float* z  = (const float*)d_in[0];
    const float* cb = (const float*)d_in[1];
    int sz0 = in_sizes[0];
    int sz1 = (n_in > 1) ? in_sizes[1] : 0;
    // robustness: codebook is the small input (K*D = 32768)
    if (sz0 < sz1) {
        const float* t = z; z = cb; cb = t;
        int ts = sz0; sz0 = sz1; sz1 = ts;
    }
    int B = sz0 / VQ_D;

    cudaFuncSetAttribute(vq_kernel, cudaFuncAttributeMaxDynamicSharedMemorySize,
                         VQ_SMEM_BYTES);
    int grid = (B + VQ_TPB - 1) / VQ_TPB;
    vq_kernel<<<grid, VQ_TPB, VQ_SMEM_BYTES>>>(z, cb, (float*)d_out, B);
}

// round 3
// speedup vs baseline: 1.3058x; 1.3058x over previous
#include <cuda_runtime.h>

// VectorQuantize, register-tiled (GEMM-style) fp32 exact version.
// B x 64 rows vs 512 x 64 codebook. Per CTA: 128 rows, all 512 codes.
// Thread tile: 8 rows x 4 codes, f32x2 packed along D.
//
// Precision contract (validated in R1, rel_err == 0.0):
//  - all scoring in fp32; dist = fl(fl(z_sq - 2*m) + c_sq)
//  - c_sq: sequential scalar fma over d ascending (identical to R1)
//  - z_sq: 4-chain pairwise f32x2, stride-4 pair interleave (identical to R1)
//  - argmin: strict '<' over ascending k within thread; lexicographic
//    (dist, k) across threads -> first-index tie break (jnp.argmin)

#define VQ_K     512
#define VQ_D     64
#define VQ_TPB   256
#define VQ_MT    128        // rows per CTA
#define VQ_RT    8          // rows per thread
#define VQ_KT    4          // codes per thread per k-sweep
#define VQ_SC    514        // cT2 dp-stride in ull (even -> 16B alignment, pad vs 512)
#define VQ_SZ    130        // zT2 dp-stride in ull
#define VQ_NIT   (VQ_K / (16 * VQ_KT))   // 8 k-sweeps

typedef unsigned long long ull;

__device__ __forceinline__ ull vq_fma2(ull a, ull b, ull c) {
    ull d;
    asm("fma.rn.f32x2 %0, %1, %2, %3;" : "=l"(d) : "l"(a), "l"(b), "l"(c));
    return d;
}
__device__ __forceinline__ ull vq_add2(ull a, ull b) {
    ull d;
    asm("add.rn.f32x2 %0, %1, %2;" : "=l"(d) : "l"(a), "l"(b));
    return d;
}
__device__ __forceinline__ float2 vq_unpack(ull a) {
    float2 f;
    asm("mov.b64 {%0, %1}, %2;" : "=f"(f.x), "=f"(f.y) : "l"(a));
    return f;
}
__device__ __forceinline__ ull vq_pack(float x, float y) {
    ull d;
    asm("mov.b64 %0, {%1, %2};" : "=l"(d) : "f"(x), "f"(y));
    return d;
}

// smem layout (bytes):
//  cT2 : 32*VQ_SC ull  = 131,584
//  zT2 : 32*VQ_SZ ull  =  33,280
//  csq : 512 f, zsq : 128 f, rd : 128*17 f, rk : 128*17 i  -> 19,968
#define VQ_CT2_ULL (32 * VQ_SC)
#define VQ_ZT2_ULL (32 * VQ_SZ)
#define VQ_SMEM_BYTES ((VQ_CT2_ULL + VQ_ZT2_ULL) * 8 + (512 + 128 + 128*17) * 4 + (128*17) * 4)

__global__ void __launch_bounds__(VQ_TPB, 1)
vq_kernel(const float* __restrict__ z, const float* __restrict__ cb,
          float* __restrict__ out, int B) {
    extern __shared__ ull sm[];
    ull*   cT2   = sm;                       // [dp*VQ_SC + k]
    ull*   zT2   = sm + VQ_CT2_ULL;          // [dp*VQ_SZ + r]
    float* s_csq = (float*)(zT2 + VQ_ZT2_ULL);   // [512]
    float* s_zsq = s_csq + VQ_K;                 // [128]
    float* s_rd  = s_zsq + VQ_MT;                // [128*17]
    int*   s_rk  = (int*)(s_rd + VQ_MT * 17);    // [128*17]

    const int tid = threadIdx.x;
    const long long base = (long long)blockIdx.x * VQ_MT;
    const int rows_in = (int)((B - base) < VQ_MT ? (B - base) : VQ_MT);

    // ---- stage codebook transposed: cT2[dp][k] = (cb[k][2dp], cb[k][2dp+1]) ----
    {
        const float4* cb4 = reinterpret_cast<const float4*>(cb);
        #pragma unroll 4
        for (int c = tid; c < VQ_K * 16; c += VQ_TPB) {
            float4 v = cb4[c];
            int k = c >> 4, dg = c & 15;
            cT2[(2 * dg)     * VQ_SC + k] = vq_pack(v.x, v.y);
            cT2[(2 * dg + 1) * VQ_SC + k] = vq_pack(v.z, v.w);
        }
    }
    // ---- stage z tile transposed: zT2[dp][r] ----
    {
        const float4* z4 = reinterpret_cast<const float4*>(z + base * VQ_D);
        #pragma unroll 2
        for (int c = tid; c < VQ_MT * 16; c += VQ_TPB) {
            int r = c >> 4, dg = c & 15;
            float4 v = (r < rows_in) ? z4[c] : make_float4(0.f, 0.f, 0.f, 0.f);
            zT2[(2 * dg)     * VQ_SZ + r] = vq_pack(v.x, v.y);
            zT2[(2 * dg + 1) * VQ_SZ + r] = vq_pack(v.z, v.w);
        }
    }
    __syncthreads();

    // ---- c_sq: sequential scalar over d ascending (== R1) ----
    #pragma unroll 1
    for (int k = tid; k < VQ_K; k += VQ_TPB) {
        float s = 0.0f;
        #pragma unroll
        for (int dp = 0; dp < 32; ++dp) {
            float2 c = vq_unpack(cT2[dp * VQ_SC + k]);
            s = __fmaf_rn(c.x, c.x, s);
            s = __fmaf_rn(c.y, c.y, s);
        }
        s_csq[k] = s;
    }
    // ---- z_sq: 4-chain pairwise, stride-4 interleave (== R1) ----
    if (tid < VQ_MT) {
        int r = tid;
        ull a0 = 0, a1 = 0, a2 = 0, a3 = 0;
        #pragma unroll
        for (int i = 0; i < 32; i += 4) {
            ull p0 = zT2[(i + 0) * VQ_SZ + r];
            ull p1 = zT2[(i + 1) * VQ_SZ + r];
            ull p2 = zT2[(i + 2) * VQ_SZ + r];
            ull p3 = zT2[(i + 3) * VQ_SZ + r];
            a0 = vq_fma2(p0, p0, a0);
            a1 = vq_fma2(p1, p1, a1);
            a2 = vq_fma2(p2, p2, a2);
            a3 = vq_fma2(p3, p3, a3);
        }
        float2 s = vq_unpack(vq_add2(vq_add2(a0, a1), vq_add2(a2, a3)));
        s_zsq[r] = __fadd_rn(s.x, s.y);
    }
    __syncthreads();

    // ---- main: 8 k-sweeps, thread tile 8 rows x 4 codes ----
    const int tx = tid & 15, ty = tid >> 4;
    const int rbase = ty * VQ_RT;

    float best[VQ_RT];
    int   bk[VQ_RT];
    #pragma unroll
    for (int r = 0; r < VQ_RT; ++r) { best[r] = __int_as_float(0x7f800000); bk[r] = 0; }

    #pragma unroll 1
    for (int it = 0; it < VQ_NIT; ++it) {
        const int k0 = it * 64 + tx * VQ_KT;
        ull acc[VQ_RT][VQ_KT];
        #pragma unroll
        for (int r = 0; r < VQ_RT; ++r)
            #pragma unroll
            for (int kk = 0; kk < VQ_KT; ++kk) acc[r][kk] = 0;

        #pragma unroll 8
        for (int dp = 0; dp < 32; ++dp) {
            const ulonglong2* cp =
                reinterpret_cast<const ulonglong2*>(cT2 + dp * VQ_SC + k0);
            ulonglong2 c01 = cp[0];
            ulonglong2 c23 = cp[1];
            ull cf[VQ_KT] = { c01.x, c01.y, c23.x, c23.y };

            const ulonglong2* zp =
                reinterpret_cast<const ulonglong2*>(zT2 + dp * VQ_SZ + rbase);
            ulonglong2 z01 = zp[0], z23 = zp[1], z45 = zp[2], z67 = zp[3];
            ull zf[VQ_RT] = { z01.x, z01.y, z23.x, z23.y, z45.x, z45.y, z67.x, z67.y };

            #pragma unroll
            for (int r = 0; r < VQ_RT; ++r)
                #pragma unroll
                for (int kk = 0; kk < VQ_KT; ++kk)
                    acc[r][kk] = vq_fma2(zf[r], cf[kk], acc[r][kk]);
        }

        // per-sweep epilogue: dist + argmin update (k ascending)
        #pragma unroll
        for (int r = 0; r < VQ_RT; ++r) {
            const float zq = s_zsq[rbase + r];
            #pragma unroll
            for (int kk = 0; kk < VQ_KT; ++kk) {
                float2 f = vq_unpack(acc[r][kk]);
                float dot  = __fadd_rn(f.x, f.y);
                float t    = __fsub_rn(zq, __fmul_rn(2.0f, dot));
                float dist = __fadd_rn(t, s_csq[k0 + kk]);
                bool p = dist < best[r];       // strict: earlier k wins ties
                best[r] = p ? dist : best[r];
                bk[r]   = p ? (k0 + kk) : bk[r];
            }
        }
    }

    // ---- cross-thread argmin reduction (lexicographic (dist, k)) ----
    #pragma unroll
    for (int r = 0; r < VQ_RT; ++r) {
        s_rd[(rbase + r) * 17 + tx] = best[r];
        s_rk[(rbase + r) * 17 + tx] = bk[r];
    }
    __syncthreads();
    if (tid < VQ_MT) {
        int r = tid;
        float bd = s_rd[r * 17 + 0];
        int   bi = s_rk[r * 17 + 0];
        #pragma unroll
        for (int t = 1; t < 16; ++t) {
            float d = s_rd[r * 17 + t];
            int   i = s_rk[r * 17 + t];
            bool p = (d < bd) || (d == bd && i < bi);
            bd = p ? d : bd;
            bi = p ? i : bi;
        }
        s_rk[r * 17] = bi;   // final winning code per row
    }
    __syncthreads();

    // ---- outputs: coalesced float4 writes; arithmetic identical to R1 ----
    float4* o1 = reinterpret_cast<float4*>(out) + base * 16;
    float4* o2 = reinterpret_cast<float4*>(out) + (long long)B * 16 + base * 16;
    #pragma unroll 2
    for (int c = tid; c < VQ_MT * 16; c += VQ_TPB) {
        int r = c >> 4, dg = c & 15;
        if (r >= rows_in) break;
        int kbest = s_rk[r * 17];
        float2 qa = vq_unpack(cT2[(2 * dg)     * VQ_SC + kbest]);
        float2 qb = vq_unpack(cT2[(2 * dg + 1) * VQ_SC + kbest]);
        float2 za = vq_unpack(zT2[(2 * dg)     * VQ_SZ + r]);
        float2 zb = vq_unpack(zT2[(2 * dg + 1) * VQ_SZ + r]);
        float4 qv = make_float4(qa.x, qa.y, qb.x, qb.y);
        float4 w;
        w.x = __fadd_rn(za.x, __fsub_rn(qa.x, za.x));
        w.y = __fadd_rn(za.y, __fsub_rn(qa.y, za.y));
        w.z = __fadd_rn(zb.x, __fsub_rn(qb.x, zb.x));
        w.w = __fadd_rn(zb.y, __fsub_rn(qb.y, zb.y));
        o1[c] = w;
        o2[c] = qv;
    }
}

extern "C" void kernel_launch(void* const* d_in, const int* in_sizes, int n_in,
                              void* d_out, int out_size) {
    const float* z  = (const float*)d_in[0];
    const float* cb = (const float*)d_in[1];
    int sz0 = in_sizes[0];
    int sz1 = (n_in > 1) ? in_sizes[1] : 0;
    if (sz0 < sz1) {   // codebook is the small input (K*D = 32768)
        const float* t = z; z = cb; cb = t;
        int ts = sz0; sz0 = sz1; sz1 = ts;
    }
    int B = sz0 / VQ_D;

    cudaFuncSetAttribute(vq_kernel, cudaFuncAttributeMaxDynamicSharedMemorySize,
                         VQ_SMEM_BYTES);
    int grid = (B + VQ_MT - 1) / VQ_MT;
    vq_kernel<<<grid, VQ_TPB, VQ_SMEM_BYTES>>>(z, cb, (float*)d_out, B);
}

// round 4
// speedup vs baseline: 1.3165x; 1.0082x over previous
#include <cuda_runtime.h>

// VectorQuantize, register-tiled fp32. B x 64 rows vs 512 x 64 codebook.
// Per CTA: 128 rows, all 512 codes. Thread tile: 8 rows x 4 codes (f32x2 on D).
//
// R4 changes vs R3 (wavefront reduction; arithmetic chains unchanged):
//  - code interleave: thread tx owns {2tx,2tx+1,32+2tx,33+2tx} per sweep
//    -> lane-contiguous LDS.128 (2 wavefronts instead of 4)
//  - cT2 stride 512 ull (128B-aligned rows), zT2 stride 128 ull
//    -> each z LDS.128 is a single wavefront
//  - staging loops minor-in-row (conflict-free STS)
//  - output epilogue reads z/cb from global (coalesced, L2) - no smem conflicts
//
// Precision contract (validated R1/R3, rel_err == 0.0): fp32 throughout,
// dist = fl(fl(z_sq - 2*dot) + c_sq); dot = single f32x2 chain over dp
// ascending then fl(x+y); z_sq 4-chain stride-4; c_sq sequential scalar;
// argmin strict '<' ascending k in-thread, lexicographic (dist,k) across.

#define VQ_K     512
#define VQ_D     64
#define VQ_TPB   256
#define VQ_MT    128
#define VQ_RT    8
#define VQ_KT    4
#define VQ_SC    512        // cT2 dp-row stride (ull) -> 4096B, 128B-aligned
#define VQ_SZ    128        // zT2 dp-row stride (ull) -> 1024B, 128B-aligned
#define VQ_NIT   8          // k-sweeps (64 codes per sweep)

typedef unsigned long long ull;

__device__ __forceinline__ ull vq_fma2(ull a, ull b, ull c) {
    ull d;
    asm("fma.rn.f32x2 %0, %1, %2, %3;" : "=l"(d) : "l"(a), "l"(b), "l"(c));
    return d;
}
__device__ __forceinline__ ull vq_add2(ull a, ull b) {
    ull d;
    asm("add.rn.f32x2 %0, %1, %2;" : "=l"(d) : "l"(a), "l"(b));
    return d;
}
__device__ __forceinline__ float2 vq_unpack(ull a) {
    float2 f;
    asm("mov.b64 {%0, %1}, %2;" : "=f"(f.x), "=f"(f.y) : "l"(a));
    return f;
}
__device__ __forceinline__ ull vq_pack(float x, float y) {
    ull d;
    asm("mov.b64 %0, {%1, %2};" : "=l"(d) : "f"(x), "f"(y));
    return d;
}

#define VQ_CT2_ULL (32 * VQ_SC)      // 16384 ull = 131072 B
#define VQ_ZT2_ULL (32 * VQ_SZ)      //  4096 ull =  32768 B
#define VQ_SMEM_BYTES ((VQ_CT2_ULL + VQ_ZT2_ULL) * 8 \
                       + (VQ_K + VQ_MT) * 4 + (VQ_MT * 17) * 8)

__global__ void __launch_bounds__(VQ_TPB, 1)
vq_kernel(const float* __restrict__ z, const float* __restrict__ cb,
          float* __restrict__ out, int B) {
    extern __shared__ ull sm[];
    ull*   cT2   = sm;                           // [dp*512 + k]
    ull*   zT2   = sm + VQ_CT2_ULL;              // [dp*128 + r]
    float* s_csq = (float*)(zT2 + VQ_ZT2_ULL);   // [512]
    float* s_zsq = s_csq + VQ_K;                 // [128]
    float* s_rd  = s_zsq + VQ_MT;                // [128*17]
    int*   s_rk  = (int*)(s_rd + VQ_MT * 17);    // [128*17]

    const int tid = threadIdx.x;
    const long long base = (long long)blockIdx.x * VQ_MT;
    const int rows_in = (int)((B - base) < VQ_MT ? (B - base) : VQ_MT);

    // ---- stage codebook transposed, k-minor (conflict-free STS) ----
    {
        const float4* cb4 = reinterpret_cast<const float4*>(cb);
        #pragma unroll 4
        for (int i = tid; i < VQ_K * 16; i += VQ_TPB) {
            int k = i & 511, dg = i >> 9;
            float4 v = cb4[k * 16 + dg];
            cT2[(2 * dg)     * VQ_SC + k] = vq_pack(v.x, v.y);
            cT2[(2 * dg + 1) * VQ_SC + k] = vq_pack(v.z, v.w);
        }
    }
    // ---- stage z tile transposed, r-minor (conflict-free STS) ----
    {
        const float4* z4 = reinterpret_cast<const float4*>(z + base * VQ_D);
        #pragma unroll 2
        for (int i = tid; i < VQ_MT * 16; i += VQ_TPB) {
            int r = i & 127, dg = i >> 7;
            float4 v = (r < rows_in) ? z4[r * 16 + dg]
                                     : make_float4(0.f, 0.f, 0.f, 0.f);
            zT2[(2 * dg)     * VQ_SZ + r] = vq_pack(v.x, v.y);
            zT2[(2 * dg + 1) * VQ_SZ + r] = vq_pack(v.z, v.w);
        }
    }
    __syncthreads();

    // ---- c_sq: sequential scalar over d ascending (chain == R1/R3) ----
    #pragma unroll 1
    for (int k = tid; k < VQ_K; k += VQ_TPB) {
        float s = 0.0f;
        #pragma unroll
        for (int dp = 0; dp < 32; ++dp) {
            float2 c = vq_unpack(cT2[dp * VQ_SC + k]);
            s = __fmaf_rn(c.x, c.x, s);
            s = __fmaf_rn(c.y, c.y, s);
        }
        s_csq[k] = s;
    }
    // ---- z_sq: 4-chain pairwise, stride-4 interleave (chain == R1/R3) ----
    if (tid < VQ_MT) {
        int r = tid;
        ull a0 = 0, a1 = 0, a2 = 0, a3 = 0;
        #pragma unroll
        for (int i = 0; i < 32; i += 4) {
            ull p0 = zT2[(i + 0) * VQ_SZ + r];
            ull p1 = zT2[(i + 1) * VQ_SZ + r];
            ull p2 = zT2[(i + 2) * VQ_SZ + r];
            ull p3 = zT2[(i + 3) * VQ_SZ + r];
            a0 = vq_fma2(p0, p0, a0);
            a1 = vq_fma2(p1, p1, a1);
            a2 = vq_fma2(p2, p2, a2);
            a3 = vq_fma2(p3, p3, a3);
        }
        float2 s = vq_unpack(vq_add2(vq_add2(a0, a1), vq_add2(a2, a3)));
        s_zsq[r] = __fadd_rn(s.x, s.y);
    }
    __syncthreads();

    // ---- main loop: 8 k-sweeps, thread tile 8 rows x 4 codes ----
    const int tx = tid & 15, ty = tid >> 4;
    const int rbase = ty * VQ_RT;

    float best[VQ_RT];
    int   bk[VQ_RT];
    #pragma unroll
    for (int r = 0; r < VQ_RT; ++r) { best[r] = __int_as_float(0x7f800000); bk[r] = 0; }

    #pragma unroll 1
    for (int it = 0; it < VQ_NIT; ++it) {
        const int K0 = it * 64;
        // thread codes (ascending): K0+2tx, K0+2tx+1, K0+32+2tx, K0+33+2tx
        const int kA = K0 + 2 * tx;        // pair {kA, kA+1}
        const int kB = kA + 32;            // pair {kB, kB+1}

        ull acc[VQ_RT][VQ_KT];
        #pragma unroll
        for (int r = 0; r < VQ_RT; ++r)
            #pragma unroll
            for (int kk = 0; kk < VQ_KT; ++kk) acc[r][kk] = 0;

        #pragma unroll 8
        for (int dp = 0; dp < 32; ++dp) {
            // lane-contiguous 16B loads: 2 wavefronts each
            ulonglong2 cA = *reinterpret_cast<const ulonglong2*>(cT2 + dp * VQ_SC + kA);
            ulonglong2 cB = *reinterpret_cast<const ulonglong2*>(cT2 + dp * VQ_SC + kB);
            ull cf[VQ_KT] = { cA.x, cA.y, cB.x, cB.y };

            // broadcast z: single-wavefront LDS.128s (128B-aligned rows)
            const ulonglong2* zp =
                reinterpret_cast<const ulonglong2*>(zT2 + dp * VQ_SZ + rbase);
            ulonglong2 z01 = zp[0], z23 = zp[1], z45 = zp[2], z67 = zp[3];
            ull zf[VQ_RT] = { z01.x, z01.y, z23.x, z23.y, z45.x, z45.y, z67.x, z67.y };

            #pragma unroll
            for (int r = 0; r < VQ_RT; ++r)
                #pragma unroll
                for (int kk = 0; kk < VQ_KT; ++kk)
                    acc[r][kk] = vq_fma2(zf[r], cf[kk], acc[r][kk]);
        }

        // per-sweep epilogue: dist + argmin (k ascending within thread)
        const int kidx[VQ_KT] = { kA, kA + 1, kB, kB + 1 };
        #pragma unroll
        for (int r = 0; r < VQ_RT; ++r) {
            const float zq = s_zsq[rbase + r];
            #pragma unroll
            for (int kk = 0; kk < VQ_KT; ++kk) {
                float2 f = vq_unpack(acc[r][kk]);
                float dot  = __fadd_rn(f.x, f.y);
                float t    = __fsub_rn(zq, __fmul_rn(2.0f, dot));
                float dist = __fadd_rn(t, s_csq[kidx[kk]]);
                bool p = dist < best[r];
                best[r] = p ? dist : best[r];
                bk[r]   = p ? kidx[kk] : bk[r];
            }
        }
    }

    // ---- cross-thread argmin reduction (lexicographic (dist, k)) ----
    #pragma unroll
    for (int r = 0; r < VQ_RT; ++r) {
        s_rd[(rbase + r) * 17 + tx] = best[r];
        s_rk[(rbase + r) * 17 + tx] = bk[r];
    }
    __syncthreads();
    if (tid < VQ_MT) {
        int r = tid;
        float bd = s_rd[r * 17 + 0];
        int   bi = s_rk[r * 17 + 0];
        #pragma unroll
        for (int t = 1; t < 16; ++t) {
            float d = s_rd[r * 17 + t];
            int   i = s_rk[r * 17 + t];
            bool p = (d < bd) || (d == bd && i < bi);
            bd = p ? d : bd;
            bi = p ? i : bi;
        }
        s_rk[r * 17] = bi;
    }
    __syncthreads();

    // ---- outputs: z and cb from GLOBAL (coalesced; L2-resident), no smem conflicts ----
    {
        const float4* cb4 = reinterpret_cast<const float4*>(cb);
        const float4* z4  = reinterpret_cast<const float4*>(z + base * VQ_D);
        float4* o1 = reinterpret_cast<float4*>(out) + base * 16;
        float4* o2 = reinterpret_cast<float4*>(out) + (long long)B * 16 + base * 16;
        #pragma unroll 2
        for (int c = tid; c < VQ_MT * 16; c += VQ_TPB) {
            int r = c >> 4, dg = c & 15;
            if (r >= rows_in) break;
            int kbest = s_rk[r * 17];
            float4 qv = cb4[kbest * 16 + dg];
            float4 zv = z4[c];
            float4 w;
            w.x = __fadd_rn(zv.x, __fsub_rn(qv.x, zv.x));
            w.y = __fadd_rn(zv.y, __fsub_rn(qv.y, zv.y));
            w.z = __fadd_rn(zv.z, __fsub_rn(qv.z, zv.z));
            w.w = __fadd_rn(zv.w, __fsub_rn(qv.w, zv.w));
            o1[c] = w;
            o2[c] = qv;
        }
    }
}

extern "C" void kernel_launch(void* const* d_in, const int* in_sizes, int n_in,
                              void* d_out, int out_size) {
    const float* z  = (const float*)d_in[0];
    const float* cb = (const float*)d_in[1];
    int sz0 = in_sizes[0];
    int sz1 = (n_in > 1) ? in_sizes[1] : 0;
    if (sz0 < sz1) {   // codebook is the small input (K*D = 32768)
        const float* t = z; z = cb; cb = t;
        int ts = sz0; sz0 = sz1; sz1 = ts;
    }
    int B = sz0 / VQ_D;

    cudaFuncSetAttribute(vq_kernel, cudaFuncAttributeMaxDynamicSharedMemorySize,
                         VQ_SMEM_BYTES);
    int grid = (B + VQ_MT - 1) / VQ_MT;
    vq_kernel<<<grid, VQ_TPB, VQ_SMEM_BYTES>>>(z, cb, (float*)d_out, B);
}

// round 7
// speedup vs baseline: 1.4605x; 1.1094x over previous
#include <cuda_runtime.h>

// VectorQuantize, register-tiled fp32. B x 64 rows vs 512 x 64 codebook.
// R5 design, final resubmit (two prior attempts died on container infra;
// round-0 stub failed identically, so error class is kernel-independent).
// 512 threads/CTA, 256 rows/CTA -> 16 warps/SM (4 per SMSP) for latency
// hiding; thread tile 8 rows x 4 codes; reduction arrays overlay zT2.
//
// Precision contract (validated R1/R3/R4, rel_err == 0.0): fp32 throughout,
// dist = fl(fl(z_sq - 2*dot) + c_sq); dot = single f32x2 chain over dp
// ascending then fl(x+y); z_sq 4-chain stride-4; c_sq sequential scalar;
// argmin strict '<' ascending k in-thread, lexicographic (dist,k) across.

#define VQ_K     512
#define VQ_D     64
#define VQ_TPB   512
#define VQ_MT    256        // rows per CTA
#define VQ_RT    8          // rows per thread
#define VQ_KT    4          // codes per thread per sweep
#define VQ_SC    512        // cT2 dp-row stride (ull) -> 4096B
#define VQ_SZ    256        // zT2 dp-row stride (ull) -> 2048B
#define VQ_NIT   8          // k-sweeps (64 codes per sweep)

typedef unsigned long long ull;

__device__ __forceinline__ ull vq_fma2(ull a, ull b, ull c) {
    ull d;
    asm("fma.rn.f32x2 %0, %1, %2, %3;" : "=l"(d) : "l"(a), "l"(b), "l"(c));
    return d;
}
__device__ __forceinline__ ull vq_add2(ull a, ull b) {
    ull d;
    asm("add.rn.f32x2 %0, %1, %2;" : "=l"(d) : "l"(a), "l"(b));
    return d;
}
__device__ __forceinline__ float2 vq_unpack(ull a) {
    float2 f;
    asm("mov.b64 {%0, %1}, %2;" : "=f"(f.x), "=f"(f.y) : "l"(a));
    return f;
}
__device__ __forceinline__ ull vq_pack(float x, float y) {
    ull d;
    asm("mov.b64 %0, {%1, %2};" : "=l"(d) : "f"(x), "f"(y));
    return d;
}

#define VQ_CT2_ULL (32 * VQ_SC)      // 16384 ull = 131072 B
#define VQ_ZT2_ULL (32 * VQ_SZ)      //  8192 ull =  65536 B
// cT2 + zT2 + csq(512f) + zsq(256f)
#define VQ_SMEM_BYTES ((VQ_CT2_ULL + VQ_ZT2_ULL) * 8 + (VQ_K + VQ_MT) * 4)
// reduction arrays (256*17 floats + 256*17 ints = 34816 B) overlay zT2

__global__ void __launch_bounds__(VQ_TPB, 1)
vq_kernel(const float* __restrict__ z, const float* __restrict__ cb,
          float* __restrict__ out, int B) {
    extern __shared__ ull sm[];
    ull*   cT2   = sm;                           // [dp*512 + k]
    ull*   zT2   = sm + VQ_CT2_ULL;              // [dp*256 + r]
    float* s_csq = (float*)(zT2 + VQ_ZT2_ULL);   // [512]
    float* s_zsq = s_csq + VQ_K;                 // [256]
    // overlay (valid only after main loop; zT2 dead by then)
    float* s_rd  = (float*)zT2;                  // [256*17]
    int*   s_rk  = (int*)(s_rd + VQ_MT * 17);    // [256*17]

    const int tid = threadIdx.x;
    const long long base = (long long)blockIdx.x * VQ_MT;
    const int rows_in = (int)((B - base) < VQ_MT ? (B - base) : VQ_MT);

    // ---- stage codebook transposed, k-minor (conflict-free STS) ----
    {
        const float4* cb4 = reinterpret_cast<const float4*>(cb);
        #pragma unroll 4
        for (int i = tid; i < VQ_K * 16; i += VQ_TPB) {
            int k = i & 511, dg = i >> 9;
            float4 v = cb4[k * 16 + dg];
            cT2[(2 * dg)     * VQ_SC + k] = vq_pack(v.x, v.y);
            cT2[(2 * dg + 1) * VQ_SC + k] = vq_pack(v.z, v.w);
        }
    }
    // ---- stage z tile transposed, r-minor (conflict-free STS) ----
    {
        const float4* z4 = reinterpret_cast<const float4*>(z + base * VQ_D);
        #pragma unroll 2
        for (int i = tid; i < VQ_MT * 16; i += VQ_TPB) {
            int r = i & 255, dg = i >> 8;
            float4 v = (r < rows_in) ? z4[r * 16 + dg]
                                     : make_float4(0.f, 0.f, 0.f, 0.f);
            zT2[(2 * dg)     * VQ_SZ + r] = vq_pack(v.x, v.y);
            zT2[(2 * dg + 1) * VQ_SZ + r] = vq_pack(v.z, v.w);
        }
    }
    __syncthreads();

    // ---- c_sq: sequential scalar over d ascending (chain == R1..R4) ----
    {
        int k = tid;
        if (k < VQ_K) {
            float s = 0.0f;
            #pragma unroll
            for (int dp = 0; dp < 32; ++dp) {
                float2 c = vq_unpack(cT2[dp * VQ_SC + k]);
                s = __fmaf_rn(c.x, c.x, s);
                s = __fmaf_rn(c.y, c.y, s);
            }
            s_csq[k] = s;
        }
    }
    // ---- z_sq: 4-chain pairwise, stride-4 interleave (chain == R1..R4) ----
    if (tid < VQ_MT) {
        int r = tid;
        ull a0 = 0, a1 = 0, a2 = 0, a3 = 0;
        #pragma unroll
        for (int i = 0; i < 32; i += 4) {
            ull p0 = zT2[(i + 0) * VQ_SZ + r];
            ull p1 = zT2[(i + 1) * VQ_SZ + r];
            ull p2 = zT2[(i + 2) * VQ_SZ + r];
            ull p3 = zT2[(i + 3) * VQ_SZ + r];
            a0 = vq_fma2(p0, p0, a0);
            a1 = vq_fma2(p1, p1, a1);
            a2 = vq_fma2(p2, p2, a2);
            a3 = vq_fma2(p3, p3, a3);
        }
        float2 s = vq_unpack(vq_add2(vq_add2(a0, a1), vq_add2(a2, a3)));
        s_zsq[r] = __fadd_rn(s.x, s.y);
    }
    __syncthreads();

    // ---- main loop: 8 k-sweeps, thread tile 8 rows x 4 codes ----
    const int tx = tid & 15, ty = tid >> 4;     // tx in [0,16), ty in [0,32)
    const int rbase = ty * VQ_RT;

    float best[VQ_RT];
    int   bk[VQ_RT];
    #pragma unroll
    for (int r = 0; r < VQ_RT; ++r) { best[r] = __int_as_float(0x7f800000); bk[r] = 0; }

    #pragma unroll 1
    for (int it = 0; it < VQ_NIT; ++it) {
        const int K0 = it * 64;
        const int kA = K0 + 2 * tx;    // pair {kA, kA+1}
        const int kB = kA + 32;        // pair {kB, kB+1}

        ull acc[VQ_RT][VQ_KT];
        #pragma unroll
        for (int r = 0; r < VQ_RT; ++r)
            #pragma unroll
            for (int kk = 0; kk < VQ_KT; ++kk) acc[r][kk] = 0;

        #pragma unroll 4
        for (int dp = 0; dp < 32; ++dp) {
            ulonglong2 cA = *reinterpret_cast<const ulonglong2*>(cT2 + dp * VQ_SC + kA);
            ulonglong2 cB = *reinterpret_cast<const ulonglong2*>(cT2 + dp * VQ_SC + kB);
            ull cf[VQ_KT] = { cA.x, cA.y, cB.x, cB.y };

            const ulonglong2* zp =
                reinterpret_cast<const ulonglong2*>(zT2 + dp * VQ_SZ + rbase);
            ulonglong2 z01 = zp[0], z23 = zp[1], z45 = zp[2], z67 = zp[3];
            ull zf[VQ_RT] = { z01.x, z01.y, z23.x, z23.y, z45.x, z45.y, z67.x, z67.y };

            #pragma unroll
            for (int r = 0; r < VQ_RT; ++r)
                #pragma unroll
                for (int kk = 0; kk < VQ_KT; ++kk)
                    acc[r][kk] = vq_fma2(zf[r], cf[kk], acc[r][kk]);
        }

        // per-sweep epilogue: dist + argmin (k ascending within thread)
        const int kidx[VQ_KT] = { kA, kA + 1, kB, kB + 1 };
        #pragma unroll
        for (int r = 0; r < VQ_RT; ++r) {
            const float zq = s_zsq[rbase + r];
            #pragma unroll
            for (int kk = 0; kk < VQ_KT; ++kk) {
                float2 f = vq_unpack(acc[r][kk]);
                float dot  = __fadd_rn(f.x, f.y);
                float t    = __fsub_rn(zq, __fmul_rn(2.0f, dot));
                float dist = __fadd_rn(t, s_csq[kidx[kk]]);
                bool p = dist < best[r];
                best[r] = p ? dist : best[r];
                bk[r]   = p ? kidx[kk] : bk[r];
            }
        }
    }

    // ---- cross-thread argmin reduction (overlay on dead zT2) ----
    __syncthreads();   // ensure all main-loop reads of zT2 are done
    #pragma unroll
    for (int r = 0; r < VQ_RT; ++r) {
        s_rd[(rbase + r) * 17 + tx] = best[r];
        s_rk[(rbase + r) * 17 + tx] = bk[r];
    }
    __syncthreads();
    if (tid < VQ_MT) {
        int r = tid;
        float bd = s_rd[r * 17 + 0];
        int   bi = s_rk[r * 17 + 0];
        #pragma unroll
        for (int t = 1; t < 16; ++t) {
            float d = s_rd[r * 17 + t];
            int   i = s_rk[r * 17 + t];
            bool p = (d < bd) || (d == bd && i < bi);
            bd = p ? d : bd;
            bi = p ? i : bi;
        }
        s_rk[r * 17] = bi;
    }
    __syncthreads();

    // ---- outputs: z and cb from GLOBAL (coalesced; L2-resident) ----
    {
        const float4* cb4 = reinterpret_cast<const float4*>(cb);
        const float4* z4  = reinterpret_cast<const float4*>(z + base * VQ_D);
        float4* o1 = reinterpret_cast<float4*>(out) + base * 16;
        float4* o2 = reinterpret_cast<float4*>(out) + (long long)B * 16 + base * 16;
        #pragma unroll 2
        for (int c = tid; c < VQ_MT * 16; c += VQ_TPB) {
            int r = c >> 4, dg = c & 15;
            if (r >= rows_in) break;
            int kbest = s_rk[r * 17];
            float4 qv = cb4[kbest * 16 + dg];
            float4 zv = z4[c];
            float4 w;
            w.x = __fadd_rn(zv.x, __fsub_rn(qv.x, zv.x));
            w.y = __fadd_rn(zv.y, __fsub_rn(qv.y, zv.y));
            w.z = __fadd_rn(zv.z, __fsub_rn(qv.z, zv.z));
            w.w = __fadd_rn(zv.w, __fsub_rn(qv.w, zv.w));
            o1[c] = w;
            o2[c] = qv;
        }
    }
}

extern "C" void kernel_launch(void* const* d_in, const int* in_sizes, int n_in,
                              void* d_out, int out_size) {
    const float* z  = (const float*)d_in[0];
    const float* cb = (const float*)d_in[1];
    int sz0 = in_sizes[0];
    int sz1 = (n_in > 1) ? in_sizes[1] : 0;
    if (sz0 < sz1) {   // codebook is the small input (K*D = 32768)
        const float* t = z; z = cb; cb = t;
        int ts = sz0; sz0 = sz1; sz1 = ts;
    }
    int B = sz0 / VQ_D;

    cudaFuncSetAttribute(vq_kernel, cudaFuncAttributeMaxDynamicSharedMemorySize,
                         VQ_SMEM_BYTES);
    int grid = (B + VQ_MT - 1) / VQ_MT;
    vq_kernel<<<grid, VQ_TPB, VQ_SMEM_BYTES>>>(z, cb, (float*)d_out, B);
}